// round 6
// baseline (speedup 1.0000x reference)
#include <cuda_runtime.h>
#include <cuda_fp16.h>
#include <mma.h>
#include <math.h>

using namespace nvcuda;

#define NMAX   50000
#define EMAX   800000
#define TOTMAX (NMAX + EMAX)
#define F      128
#define NPAD   (NMAX + 128)   // slack so tail-block wmma stores can't overflow

// ---------------- device scratch (no allocations allowed) ----------------
__device__ float g_xp[NPAD * F];        // x @ W (fp32, for dots / reference)
__device__ uint2 g_xph[NMAX * 32];      // x @ W in half2: row = 32 x uint2 (128 halves)
__device__ float g_asrc[NMAX];          // xp . att_src
__device__ float g_adst[NMAX];          // xp . att_dst
__device__ int   g_deg[NMAX];           // per-dst degree (incl self loop)
__device__ int   g_offs[NMAX + 1];      // CSR offsets
__device__ int   g_rank[EMAX];          // per-edge rank within its dst segment
__device__ int   g_csr[TOTMAX];         // CSR: source node per slot
__device__ int   g_is64;                // edge_index dtype flag

// ---------------- edge dtype probe (parallel, 1 warp) ----------------
__global__ void probe_kernel(const unsigned int* __restrict__ w, int E) {
    int samples = E < 1024 ? E : 1024;
    int bad = 0;
    for (int k = threadIdx.x; k < samples; k += 32)
        bad |= (w[2 * k + 1] != 0u) ? 1 : 0;
    unsigned int b = __ballot_sync(0xffffffffu, bad);
    if (threadIdx.x == 0) g_is64 = (b == 0u) ? 1 : 0;
}

__device__ __forceinline__ int edge_at(const void* ebuf, long long idx, int is64) {
    if (is64) return (int)((const long long*)ebuf)[idx];
    return ((const int*)ebuf)[idx];
}

// ---------------- degree init (self loop = 1) ----------------
__global__ void init_deg_kernel(int N) {
    int i = blockIdx.x * blockDim.x + threadIdx.x;
    if (i < N) g_deg[i] = 1;
}

// ---------------- histogram of dst + per-edge rank ----------------
__global__ void hist_kernel(const void* __restrict__ edges, int E) {
    int e = blockIdx.x * blockDim.x + threadIdx.x;
    if (e >= E) return;
    int is64 = g_is64;
    int d = edge_at(edges, (long long)E + e, is64);
    g_rank[e] = atomicAdd(&g_deg[d], 1);   // old value >= 1 (slot 0 = self loop)
}

// ---------------- GEMM (wmma tf32) + fused dots + half2 mirror ----------------
#define BM 128
#define BK 32
#define LDA 40    // 32 + 8 pad
#define LDB 136   // 128 + 8 pad
__global__ __launch_bounds__(256)
void gemm_kernel(const float* __restrict__ x, const float* __restrict__ W,
                 const float* __restrict__ att_src, const float* __restrict__ att_dst,
                 int N) {
    __shared__ float As[BM * LDA];
    __shared__ float Bs[BK * LDB];

    int tid  = threadIdx.x;
    int warp = tid >> 5;
    int lane = tid & 31;
    int warp_m = warp >> 1;
    int warp_n = warp & 1;
    int row0 = blockIdx.x * BM;

    wmma::fragment<wmma::accumulator, 16, 16, 8, float> acc[2][4];
#pragma unroll
    for (int mt = 0; mt < 2; mt++)
#pragma unroll
        for (int nt = 0; nt < 4; nt++)
            wmma::fill_fragment(acc[mt][nt], 0.0f);

    const float4* x4 = (const float4*)x;
    const float4* W4 = (const float4*)W;

    for (int kb = 0; kb < 4; kb++) {
#pragma unroll
        for (int i = tid; i < BM * 8; i += 256) {
            int m = i >> 3, kq = i & 7;
            int gr = row0 + m;
            float4 v = (gr < N) ? x4[(long long)gr * 32 + kb * 8 + kq]
                                : make_float4(0.f, 0.f, 0.f, 0.f);
            float* dst = &As[m * LDA + kq * 4];
            dst[0] = wmma::__float_to_tf32(v.x);
            dst[1] = wmma::__float_to_tf32(v.y);
            dst[2] = wmma::__float_to_tf32(v.z);
            dst[3] = wmma::__float_to_tf32(v.w);
        }
#pragma unroll
        for (int i = tid; i < BK * 32; i += 256) {
            int k = i >> 5, nq = i & 31;
            float4 v = W4[(long long)(kb * 32 + k) * 32 + nq];
            float* dst = &Bs[k * LDB + nq * 4];
            dst[0] = wmma::__float_to_tf32(v.x);
            dst[1] = wmma::__float_to_tf32(v.y);
            dst[2] = wmma::__float_to_tf32(v.z);
            dst[3] = wmma::__float_to_tf32(v.w);
        }
        __syncthreads();

#pragma unroll
        for (int kk = 0; kk < 4; kk++) {
            wmma::fragment<wmma::matrix_a, 16, 16, 8, wmma::precision::tf32, wmma::row_major> af[2];
            wmma::fragment<wmma::matrix_b, 16, 16, 8, wmma::precision::tf32, wmma::row_major> bf[4];
#pragma unroll
            for (int mt = 0; mt < 2; mt++)
                wmma::load_matrix_sync(af[mt], &As[(warp_m * 32 + mt * 16) * LDA + kk * 8], LDA);
#pragma unroll
            for (int nt = 0; nt < 4; nt++)
                wmma::load_matrix_sync(bf[nt], &Bs[(kk * 8) * LDB + warp_n * 64 + nt * 16], LDB);
#pragma unroll
            for (int mt = 0; mt < 2; mt++)
#pragma unroll
                for (int nt = 0; nt < 4; nt++)
                    wmma::mma_sync(acc[mt][nt], af[mt], bf[nt], acc[mt][nt]);
        }
        __syncthreads();
    }

#pragma unroll
    for (int mt = 0; mt < 2; mt++)
#pragma unroll
        for (int nt = 0; nt < 4; nt++)
            wmma::store_matrix_sync(
                &g_xp[(long long)(row0 + warp_m * 32 + mt * 16) * F + warp_n * 64 + nt * 16],
                acc[mt][nt], F, wmma::mem_row_major);

    __syncthreads();

    // fused epilogue: attention dots (fp32) + half2 mirror of xp rows (L1-hot)
    {
        float4 a = ((const float4*)att_src)[lane];
        float4 b = ((const float4*)att_dst)[lane];
        const float4* xp4 = (const float4*)g_xp;
#pragma unroll
        for (int r = 0; r < 16; r++) {
            int gr = row0 + warp * 16 + r;
            if (gr >= N) break;
            float4 v = xp4[(long long)gr * 32 + lane];

            // half2 mirror: lane covers features [lane*4, lane*4+4)
            __half2 h0 = __floats2half2_rn(v.x, v.y);
            __half2 h1 = __floats2half2_rn(v.z, v.w);
            uint2 u;
            u.x = *(unsigned int*)&h0;
            u.y = *(unsigned int*)&h1;
            g_xph[gr * 32 + lane] = u;

            float ps = v.x * a.x + v.y * a.y + v.z * a.z + v.w * a.w;
            float pd = v.x * b.x + v.y * b.y + v.z * b.z + v.w * b.w;
#pragma unroll
            for (int o = 16; o; o >>= 1) {
                ps += __shfl_down_sync(0xffffffffu, ps, o);
                pd += __shfl_down_sync(0xffffffffu, pd, o);
            }
            if (lane == 0) { g_asrc[gr] = ps; g_adst[gr] = pd; }
        }
    }
}

// ---------------- exclusive scan + self-loop placement (1 block) ----------------
__global__ void scan_kernel(int N) {
    __shared__ int sh[1024];
    int tid = threadIdx.x;
    int chunk = (N + 1023) >> 10;
    int beg = tid * chunk;
    int end = beg + chunk; if (end > N) end = N;

    int s = 0;
    for (int i = beg; i < end; i++) s += g_deg[i];
    sh[tid] = s;
    __syncthreads();
    for (int o = 1; o < 1024; o <<= 1) {
        int v = (tid >= o) ? sh[tid - o] : 0;
        __syncthreads();
        sh[tid] += v;
        __syncthreads();
    }
    int run = sh[tid] - s;
    for (int i = beg; i < end; i++) {
        g_offs[i] = run;
        g_csr[run] = i;         // self loop at slot 0 of each segment
        run += g_deg[i];
    }
    if (tid == 1023) g_offs[N] = sh[1023];
}

// ---------------- CSR fill (atomic-free via precomputed rank) ----------------
__global__ void fill_kernel(const void* __restrict__ edges, int E) {
    int e = blockIdx.x * blockDim.x + threadIdx.x;
    if (e >= E) return;
    int is64 = g_is64;
    int s = edge_at(edges, e, is64);
    int d = edge_at(edges, (long long)E + e, is64);
    g_csr[__ldg(&g_offs[d]) + g_rank[e]] = s;
}

// ---------------- aggregate: warp per dst, half2 gather (256B/row) ------------
__global__ void aggregate_kernel(const float* __restrict__ bias,
                                 float* __restrict__ out, int N) {
    int warp = (blockIdx.x * blockDim.x + threadIdx.x) >> 5;
    int lane = threadIdx.x & 31;
    if (warp >= N) return;

    int beg = g_offs[warp];
    int end = g_offs[warp + 1];
    float adi = g_adst[warp];

    float s = 0.f;
    float4 acc = make_float4(0.f, 0.f, 0.f, 0.f);

    for (int c = beg; c < end; c += 32) {
        int idx = c + lane;
        bool valid = idx < end;
        int j = __ldg(&g_csr[valid ? idx : beg]);
        float e = __ldg(&g_asrc[j]) + adi;
        e = fmaxf(e, 0.2f * e);              // leaky_relu(0.2)
        float p = valid ? __expf(e) : 0.f;

        int cnt = end - c; if (cnt > 32) cnt = 32;
#pragma unroll 8
        for (int t = 0; t < cnt; t++) {
            int jj   = __shfl_sync(0xffffffffu, j, t);
            float pp = __shfl_sync(0xffffffffu, p, t);
            uint2 u = g_xph[jj * 32 + lane];
            float2 f0 = __half22float2(*(__half2*)&u.x);
            float2 f1 = __half22float2(*(__half2*)&u.y);
            s += pp;
            acc.x = fmaf(pp, f0.x, acc.x);
            acc.y = fmaf(pp, f0.y, acc.y);
            acc.z = fmaf(pp, f1.x, acc.z);
            acc.w = fmaf(pp, f1.y, acc.w);
        }
    }

    float inv = 1.0f / s;
    float4 b = ((const float4*)bias)[lane];
    float4 o;
    o.x = fmaf(acc.x, inv, b.x);
    o.y = fmaf(acc.y, inv, b.y);
    o.z = fmaf(acc.z, inv, b.z);
    o.w = fmaf(acc.w, inv, b.w);
    ((float4*)out)[(long long)warp * 32 + lane] = o;
}

// ---------------- launch ----------------
extern "C" void kernel_launch(void* const* d_in, const int* in_sizes, int n_in,
                              void* d_out, int out_size) {
    const float* x       = (const float*)d_in[0];
    const float* W       = (const float*)d_in[1];
    const float* att_src = (const float*)d_in[2];
    const float* att_dst = (const float*)d_in[3];
    const float* bias    = (const float*)d_in[4];
    const void*  edges   = d_in[5];

    int N = in_sizes[0] / F;
    int E = in_sizes[5] / 2;
    if (N > NMAX) N = NMAX;
    if (E > EMAX) E = EMAX;

    probe_kernel<<<1, 32>>>((const unsigned int*)edges, E);
    init_deg_kernel<<<(N + 255) / 256, 256>>>(N);
    hist_kernel<<<(E + 255) / 256, 256>>>(edges, E);
    gemm_kernel<<<(N + BM - 1) / BM, 256>>>(x, W, att_src, att_dst, N);
    scan_kernel<<<1, 1024>>>(N);
    fill_kernel<<<(E + 255) / 256, 256>>>(edges, E);
    aggregate_kernel<<<(N + 7) / 8, 256>>>(bias, (float*)d_out, N);
}

// round 7
// speedup vs baseline: 1.6030x; 1.6030x over previous
#include <cuda_runtime.h>
#include <cuda_pipeline.h>
#include <mma.h>
#include <math.h>

using namespace nvcuda;

#define NMAX   50000
#define EMAX   800000
#define TOTMAX (NMAX + EMAX)
#define F      128
#define NPAD   (NMAX + 128)   // slack so tail-block wmma stores can't overflow

// ---------------- device scratch (no allocations allowed) ----------------
__device__ float g_xp[NPAD * F];        // x @ W
__device__ float g_asrc[NMAX];          // xp . att_src
__device__ float g_adst[NMAX];          // xp . att_dst
__device__ int   g_deg[NMAX];           // per-dst degree (incl self loop)
__device__ int   g_offs[NMAX + 1];      // CSR offsets
__device__ int   g_rank[EMAX];          // per-edge rank within its dst segment
__device__ int   g_csr[TOTMAX];         // CSR: source node per slot
__device__ int   g_bsum[256];           // scan: per-block sums
__device__ int   g_boff[256];           // scan: per-block exclusive offsets
__device__ int   g_is64;                // edge_index dtype flag

// ---------------- fused probe (1 warp of block 0) + degree init ----------------
// int64 layout: high word of every element is 0 (values < 50000).
__global__ void probe_init_kernel(const unsigned int* __restrict__ w, int E, int N) {
    int i = blockIdx.x * blockDim.x + threadIdx.x;
    if (i < N) g_deg[i] = 1;                       // self loop
    if (blockIdx.x == 0 && threadIdx.x < 32) {
        int samples = E < 1024 ? E : 1024;
        int bad = 0;
        for (int k = threadIdx.x; k < samples; k += 32)
            bad |= (w[2 * k + 1] != 0u) ? 1 : 0;
        unsigned int b = __ballot_sync(0xffffffffu, bad);
        if (threadIdx.x == 0) g_is64 = (b == 0u) ? 1 : 0;
    }
}

__device__ __forceinline__ int edge_at(const void* ebuf, long long idx, int is64) {
    if (is64) return (int)((const long long*)ebuf)[idx];
    return ((const int*)ebuf)[idx];
}

// ---------------- histogram of dst + per-edge rank ----------------
__global__ void hist_kernel(const void* __restrict__ edges, int E) {
    int e = blockIdx.x * blockDim.x + threadIdx.x;
    if (e >= E) return;
    int is64 = g_is64;
    int d = edge_at(edges, (long long)E + e, is64);
    g_rank[e] = atomicAdd(&g_deg[d], 1);   // old value >= 1 (slot 0 = self loop)
}

// ---------------- GEMM (wmma tf32, cp.async pipelined) + fused dots ----------
// BM=128, BN=128. W (128x128) staged once in smem; A double-buffered per BK=32.
// tf32 conversion happens on fragment registers after ldmatrix.
#define BM 128
#define BK 32
#define LDA 40    // 32 + 8 pad
#define LDB 136   // 128 + 8 pad
#define GEMM_SMEM_FLOATS (128 * LDB + 2 * BM * LDA)
#define GEMM_SMEM_BYTES  (GEMM_SMEM_FLOATS * 4)

__global__ __launch_bounds__(256)
void gemm_kernel(const float* __restrict__ x, const float* __restrict__ W,
                 const float* __restrict__ att_src, const float* __restrict__ att_dst,
                 int N) {
    extern __shared__ float smem[];
    float* Ws = smem;                    // [128][LDB]
    float* As = smem + 128 * LDB;        // [2][BM][LDA]

    int tid  = threadIdx.x;
    int warp = tid >> 5;
    int lane = tid & 31;
    int warp_m = warp >> 1;
    int warp_n = warp & 1;
    int row0 = blockIdx.x * BM;

    // stage A chunk kb into buffer buf (async)
    auto stageA = [&](int kb, int buf) {
        float* base = As + buf * BM * LDA;
#pragma unroll
        for (int it = 0; it < 4; it++) {
            int item = tid + it * 256;       // 1024 items = 128 rows x 8 float4
            int m = item >> 3, kq = item & 7;
            int gr = row0 + m;
            float* dst = base + m * LDA + kq * 4;
            if (gr < N) {
                __pipeline_memcpy_async(dst, x + (long long)gr * F + kb * 32 + kq * 4, 16);
            } else {
                dst[0] = 0.f; dst[1] = 0.f; dst[2] = 0.f; dst[3] = 0.f;
            }
        }
        __pipeline_commit();
    };

    stageA(0, 0);
    // stage full W: 128 rows x 32 float4 = 4096 items
#pragma unroll
    for (int it = 0; it < 16; it++) {
        int item = tid + it * 256;
        int k = item >> 5, nq = item & 31;
        __pipeline_memcpy_async(Ws + k * LDB + nq * 4, W + (long long)k * F + nq * 4, 16);
    }
    __pipeline_commit();

    wmma::fragment<wmma::accumulator, 16, 16, 8, float> acc[2][4];
#pragma unroll
    for (int mt = 0; mt < 2; mt++)
#pragma unroll
        for (int nt = 0; nt < 4; nt++)
            wmma::fill_fragment(acc[mt][nt], 0.0f);

    __pipeline_wait_prior(0);
    __syncthreads();

    for (int kb = 0; kb < 4; kb++) {
        if (kb < 3) stageA(kb + 1, (kb + 1) & 1);   // overlap with compute below
        const float* Abuf = As + (kb & 1) * BM * LDA;

#pragma unroll
        for (int kk = 0; kk < 4; kk++) {
            wmma::fragment<wmma::matrix_a, 16, 16, 8, wmma::precision::tf32, wmma::row_major> af[2];
            wmma::fragment<wmma::matrix_b, 16, 16, 8, wmma::precision::tf32, wmma::row_major> bf[4];
#pragma unroll
            for (int mt = 0; mt < 2; mt++) {
                wmma::load_matrix_sync(af[mt], Abuf + (warp_m * 32 + mt * 16) * LDA + kk * 8, LDA);
#pragma unroll
                for (int i = 0; i < af[mt].num_elements; i++)
                    af[mt].x[i] = wmma::__float_to_tf32(af[mt].x[i]);
            }
#pragma unroll
            for (int nt = 0; nt < 4; nt++) {
                wmma::load_matrix_sync(bf[nt], Ws + (kb * 32 + kk * 8) * LDB + warp_n * 64 + nt * 16, LDB);
#pragma unroll
                for (int i = 0; i < bf[nt].num_elements; i++)
                    bf[nt].x[i] = wmma::__float_to_tf32(bf[nt].x[i]);
            }
#pragma unroll
            for (int mt = 0; mt < 2; mt++)
#pragma unroll
                for (int nt = 0; nt < 4; nt++)
                    wmma::mma_sync(acc[mt][nt], af[mt], bf[nt], acc[mt][nt]);
        }

        if (kb < 3) { __pipeline_wait_prior(0); __syncthreads(); }
    }

#pragma unroll
    for (int mt = 0; mt < 2; mt++)
#pragma unroll
        for (int nt = 0; nt < 4; nt++)
            wmma::store_matrix_sync(
                &g_xp[(long long)(row0 + warp_m * 32 + mt * 16) * F + warp_n * 64 + nt * 16],
                acc[mt][nt], F, wmma::mem_row_major);

    __syncthreads();

    // fused attention dots: warp w handles rows row0 + w*16 .. +15
    {
        float4 a = ((const float4*)att_src)[lane];
        float4 b = ((const float4*)att_dst)[lane];
        const float4* xp4 = (const float4*)g_xp;
#pragma unroll
        for (int r = 0; r < 16; r++) {
            int gr = row0 + warp * 16 + r;
            if (gr >= N) break;
            float4 v = xp4[(long long)gr * 32 + lane];
            float ps = v.x * a.x + v.y * a.y + v.z * a.z + v.w * a.w;
            float pd = v.x * b.x + v.y * b.y + v.z * b.z + v.w * b.w;
#pragma unroll
            for (int o = 16; o; o >>= 1) {
                ps += __shfl_down_sync(0xffffffffu, ps, o);
                pd += __shfl_down_sync(0xffffffffu, pd, o);
            }
            if (lane == 0) { g_asrc[gr] = ps; g_adst[gr] = pd; }
        }
    }
}

// ---------------- parallel scan: A) block sums ----------------
__global__ void scanA_kernel(int N) {
    __shared__ int sh[256];
    int t = threadIdx.x;
    int i = blockIdx.x * 256 + t;
    sh[t] = (i < N) ? g_deg[i] : 0;
    __syncthreads();
    for (int o = 128; o; o >>= 1) {
        if (t < o) sh[t] += sh[t + o];
        __syncthreads();
    }
    if (t == 0) g_bsum[blockIdx.x] = sh[0];
}

// ---------------- parallel scan: B) scan of block sums (1 block) --------------
__global__ void scanB_kernel(int nb, int N) {
    __shared__ int sh[256];
    int t = threadIdx.x;
    int v = (t < nb) ? g_bsum[t] : 0;
    sh[t] = v;
    __syncthreads();
    for (int o = 1; o < 256; o <<= 1) {
        int u = (t >= o) ? sh[t - o] : 0;
        __syncthreads();
        sh[t] += u;
        __syncthreads();
    }
    if (t < nb) g_boff[t] = sh[t] - v;      // exclusive
    if (t == 255) g_offs[N] = sh[255];      // total
}

// ---------------- parallel scan: C) apply + self-loop placement ---------------
__global__ void scanC_kernel(int N) {
    __shared__ int sh[256];
    int t = threadIdx.x;
    int i = blockIdx.x * 256 + t;
    int v = (i < N) ? g_deg[i] : 0;
    sh[t] = v;
    __syncthreads();
    for (int o = 1; o < 256; o <<= 1) {
        int u = (t >= o) ? sh[t - o] : 0;
        __syncthreads();
        sh[t] += u;
        __syncthreads();
    }
    if (i < N) {
        int off = g_boff[blockIdx.x] + sh[t] - v;
        g_offs[i] = off;
        g_csr[off] = i;                      // self loop at slot 0 of segment
    }
}

// ---------------- CSR fill (atomic-free via precomputed rank) ----------------
__global__ void fill_kernel(const void* __restrict__ edges, int E) {
    int e = blockIdx.x * blockDim.x + threadIdx.x;
    if (e >= E) return;
    int is64 = g_is64;
    int s = edge_at(edges, e, is64);
    int d = edge_at(edges, (long long)E + e, is64);
    g_csr[__ldg(&g_offs[d]) + g_rank[e]] = s;
}

// ---------------- aggregate: warp per dst, chunked cooperative prefetch -------
// Logits are O(10) -> expf cannot overflow; no max shift needed.
__global__ void aggregate_kernel(const float* __restrict__ bias,
                                 float* __restrict__ out, int N) {
    int warp = (blockIdx.x * blockDim.x + threadIdx.x) >> 5;
    int lane = threadIdx.x & 31;
    if (warp >= N) return;

    int beg = g_offs[warp];
    int end = g_offs[warp + 1];
    float adi = g_adst[warp];

    float s = 0.f;
    float4 acc = make_float4(0.f, 0.f, 0.f, 0.f);
    const float4* xp4 = (const float4*)g_xp;

    for (int c = beg; c < end; c += 32) {
        int idx = c + lane;
        bool valid = idx < end;
        int j = __ldg(&g_csr[valid ? idx : beg]);
        float e = __ldg(&g_asrc[j]) + adi;
        e = fmaxf(e, 0.2f * e);              // leaky_relu(0.2)
        float p = valid ? __expf(e) : 0.f;

        int cnt = end - c; if (cnt > 32) cnt = 32;
#pragma unroll 8
        for (int t = 0; t < cnt; t++) {
            int jj   = __shfl_sync(0xffffffffu, j, t);
            float pp = __shfl_sync(0xffffffffu, p, t);
            float4 xv = xp4[(long long)jj * 32 + lane];
            s += pp;
            acc.x = fmaf(pp, xv.x, acc.x);
            acc.y = fmaf(pp, xv.y, acc.y);
            acc.z = fmaf(pp, xv.z, acc.z);
            acc.w = fmaf(pp, xv.w, acc.w);
        }
    }

    float inv = 1.0f / s;
    float4 b = ((const float4*)bias)[lane];
    float4 o;
    o.x = fmaf(acc.x, inv, b.x);
    o.y = fmaf(acc.y, inv, b.y);
    o.z = fmaf(acc.z, inv, b.z);
    o.w = fmaf(acc.w, inv, b.w);
    ((float4*)out)[(long long)warp * 32 + lane] = o;
}

// ---------------- launch ----------------
extern "C" void kernel_launch(void* const* d_in, const int* in_sizes, int n_in,
                              void* d_out, int out_size) {
    const float* x       = (const float*)d_in[0];
    const float* W       = (const float*)d_in[1];
    const float* att_src = (const float*)d_in[2];
    const float* att_dst = (const float*)d_in[3];
    const float* bias    = (const float*)d_in[4];
    const void*  edges   = d_in[5];

    int N = in_sizes[0] / F;
    int E = in_sizes[5] / 2;
    if (N > NMAX) N = NMAX;
    if (E > EMAX) E = EMAX;

    int nb = (N + 255) / 256;   // scan blocks (<= 256)

    cudaFuncSetAttribute(gemm_kernel, cudaFuncAttributeMaxDynamicSharedMemorySize,
                         GEMM_SMEM_BYTES);

    probe_init_kernel<<<(N + 255) / 256, 256>>>((const unsigned int*)edges, E, N);
    hist_kernel<<<(E + 255) / 256, 256>>>(edges, E);
    gemm_kernel<<<(N + BM - 1) / BM, 256, GEMM_SMEM_BYTES>>>(x, W, att_src, att_dst, N);
    scanA_kernel<<<nb, 256>>>(N);
    scanB_kernel<<<1, 256>>>(nb, N);
    scanC_kernel<<<nb, 256>>>(N);
    fill_kernel<<<(E + 255) / 256, 256>>>(edges, E);
    aggregate_kernel<<<(N + 7) / 8, 256>>>(bias, (float*)d_out, N);
}